// round 13
// baseline (speedup 1.0000x reference)
#include <cuda_runtime.h>

// LightGCN 3-layer propagation + batched lookup — Round 13.
// R12 structure (bucket CSR, best: 281.3us) + k_layer instruction diet:
// 32-bit indexing, pre-multiplied row offsets through the shuffle,
// exact-grid (no guard), __launch_bounds__.

constexpr int N_USERS = 200000;
constexpr int N_ITEMS = 100000;
constexpr int N_EDGES = 1000000;
constexpr int NT      = N_USERS + N_ITEMS;   // 300,000 destination nodes
constexpr int DV      = 16;                  // 64 floats = 16 float4
constexpr int BATCH   = 8192;
constexpr int CAPLOG  = 6;                   // bucket capacity 64
constexpr int CAP     = 1 << CAPLOG;

constexpr int NU4 = N_USERS * DV;
constexpr int NI4 = N_ITEMS * DV;

__device__ float4 g_u[3][NU4];
__device__ float4 g_i[3][NI4];
__device__ int    g_cnt[NT];
__device__ int2   g_csr[(long long)NT << CAPLOG];  // bucketed: node n at n<<6

// ---------------- preprocessing ----------------

__global__ void k_zero_cnt() {
    int t = blockIdx.x * blockDim.x + threadIdx.x;
    if (t * 4 < NT) *(int4*)&g_cnt[t * 4] = make_int4(0, 0, 0, 0);
}

// One edge per thread: 2 counter bumps + 2 bucket stores.
__global__ void k_permute(const int* __restrict__ eu, const int* __restrict__ ei,
                          const float* __restrict__ nrm) {
    int e = blockIdx.x * blockDim.x + threadIdx.x;
    if (e >= N_EDGES) return;
    int u = __ldg(eu + e);
    int i = __ldg(ei + e);
    int wbits = __float_as_int(__ldg(nrm + e));
    int ni = N_USERS + i;
    int s1 = atomicAdd(&g_cnt[ni], 1);            // item dst <- user src
    g_csr[(ni << CAPLOG) + s1] = make_int2(u, wbits);
    int s2 = atomicAdd(&g_cnt[u], 1);             // user dst <- item src
    g_csr[(u << CAPLOG) + s2] = make_int2(i, wbits);
}

// ---------------- propagation layer: coop-CSR + shuffle, 32-bit math --------
// 16 lanes per node; lanes jointly load up to 16 CSR entries (coalesced),
// pre-multiply row offsets, distribute via shfl; 1 row load per edge.

__global__ void __launch_bounds__(256)
k_layer(const float4* __restrict__ uf, const float4* __restrict__ itf, int layer) {
    int t = blockIdx.x * blockDim.x + threadIdx.x;
    int n = t >> 4;
    int lane = t & 15;
    int half = (threadIdx.x >> 4) & 1;
    unsigned hmask = 0xFFFFu << (half * 16);

    const float4* src;
    float4* dst;
    if (n < N_USERS) {
        src = (layer == 0) ? itf : g_i[layer - 1];
        dst = &g_u[layer][(n << 4) + lane];
    } else {
        src = (layer == 0) ? uf : g_u[layer - 1];
        dst = &g_i[layer][((n - N_USERS) << 4) + lane];
    }

    int beg = n << CAPLOG;
    int deg = __ldg(&g_cnt[n]);
    int end = beg + deg;

    float4 acc0 = make_float4(0.f, 0.f, 0.f, 0.f);
    float4 acc1 = acc0;

    for (int base = beg; base < end; base += 16) {
        int k = base + lane;
        int2 p = (k < end) ? __ldg(&g_csr[k]) : make_int2(0, 0);
        int poff = p.x << 4;                 // pre-multiplied row offset
        int cnt = end - base;
        if (cnt > 16) cnt = 16;

        int m = 0;
        for (; m + 1 < cnt; m += 2) {
            int   s0 = __shfl_sync(hmask, poff, m,     16);
            int   w0b= __shfl_sync(hmask, p.y,  m,     16);
            int   s1 = __shfl_sync(hmask, poff, m + 1, 16);
            int   w1b= __shfl_sync(hmask, p.y,  m + 1, 16);
            float4 r0 = __ldg(src + s0 + lane);
            float4 r1 = __ldg(src + s1 + lane);
            float w0 = __int_as_float(w0b);
            float w1 = __int_as_float(w1b);
            acc0.x += r0.x * w0; acc0.y += r0.y * w0; acc0.z += r0.z * w0; acc0.w += r0.w * w0;
            acc1.x += r1.x * w1; acc1.y += r1.y * w1; acc1.z += r1.z * w1; acc1.w += r1.w * w1;
        }
        if (m < cnt) {
            int   s0 = __shfl_sync(hmask, poff, m, 16);
            int   w0b= __shfl_sync(hmask, p.y,  m, 16);
            float4 r0 = __ldg(src + s0 + lane);
            float w0 = __int_as_float(w0b);
            acc0.x += r0.x * w0; acc0.y += r0.y * w0; acc0.z += r0.z * w0; acc0.w += r0.w * w0;
        }
    }

    *dst = make_float4(acc0.x + acc1.x, acc0.y + acc1.y,
                       acc0.z + acc1.z, acc0.w + acc1.w);
}

// ---------------- final batched lookup ----------------

__global__ void k_gather(const float4* __restrict__ uf, const float4* __restrict__ itf,
                         const int* __restrict__ users, const int* __restrict__ pos,
                         const int* __restrict__ neg, float4* __restrict__ out) {
    int t = blockIdx.x * blockDim.x + threadIdx.x;
    const int total = 3 * BATCH * DV;
    if (t >= total) return;
    int sec  = t / (BATCH * DV);
    int rem  = t % (BATCH * DV);
    int r    = rem / DV;
    int lane = rem % DV;

    float4 acc;
    if (sec == 0) {
        int idx = (__ldg(users + r) << 4) + lane;
        float4 a = uf[idx], b = g_u[0][idx], c = g_u[1][idx], d = g_u[2][idx];
        acc = make_float4(a.x + b.x + c.x + d.x, a.y + b.y + c.y + d.y,
                          a.z + b.z + c.z + d.z, a.w + b.w + c.w + d.w);
    } else {
        int idx = (((sec == 1) ? __ldg(pos + r) : __ldg(neg + r)) << 4) + lane;
        float4 a = itf[idx], b = g_i[0][idx], c = g_i[1][idx], d = g_i[2][idx];
        acc = make_float4(a.x + b.x + c.x + d.x, a.y + b.y + c.y + d.y,
                          a.z + b.z + c.z + d.z, a.w + b.w + c.w + d.w);
    }
    const float s = 0.25f;
    out[t] = make_float4(acc.x * s, acc.y * s, acc.z * s, acc.w * s);
}

extern "C" void kernel_launch(void* const* d_in, const int* in_sizes, int n_in,
                              void* d_out, int out_size) {
    const float4* user_feat = (const float4*)d_in[0];
    const float4* item_feat = (const float4*)d_in[1];
    const int*    edge_u    = (const int*)d_in[2];
    const int*    edge_i    = (const int*)d_in[3];
    const float*  nrm       = (const float*)d_in[4];
    const int*    users     = (const int*)d_in[5];
    const int*    pos       = (const int*)d_in[6];
    const int*    neg       = (const int*)d_in[7];
    float4*       out       = (float4*)d_out;

    const int TPB = 256;

    k_zero_cnt<<<(NT / 4 + TPB - 1) / TPB, TPB>>>();
    k_permute<<<(N_EDGES + TPB - 1) / TPB, TPB>>>(edge_u, edge_i, nrm);

    const int lt = NT * DV;                       // 4.8M threads, exact
    const int layer_blocks = lt / TPB;
    for (int l = 0; l < 3; l++)
        k_layer<<<layer_blocks, TPB>>>(user_feat, item_feat, l);

    const int gt_total = 3 * BATCH * DV;
    k_gather<<<(gt_total + TPB - 1) / TPB, TPB>>>(user_feat, item_feat, users, pos, neg, out);
}

// round 14
// speedup vs baseline: 1.1241x; 1.1241x over previous
#include <cuda_runtime.h>

// LightGCN 3-layer propagation + batched lookup — Round 14.
// R12 preprocessing (bucket CSR, best) + k_layer remapped to 8 lanes/node x
// 2 float4 columns per lane -> 4 independent row loads in flight per thread
// (pure MLP doubling, zero wasted iterations).

constexpr int N_USERS = 200000;
constexpr int N_ITEMS = 100000;
constexpr int N_EDGES = 1000000;
constexpr int NT      = N_USERS + N_ITEMS;   // 300,000 destination nodes
constexpr int DV      = 16;                  // 64 floats = 16 float4
constexpr int BATCH   = 8192;
constexpr int CAPLOG  = 6;                   // bucket capacity 64
constexpr int CAP     = 1 << CAPLOG;

constexpr int NU4 = N_USERS * DV;
constexpr int NI4 = N_ITEMS * DV;

__device__ float4 g_u[3][NU4];
__device__ float4 g_i[3][NI4];
__device__ int    g_cnt[NT];
__device__ int2   g_csr[(long long)NT << CAPLOG];  // bucketed: node n at n<<6

// ---------------- preprocessing ----------------

__global__ void k_zero_cnt() {
    int t = blockIdx.x * blockDim.x + threadIdx.x;
    if (t * 4 < NT) *(int4*)&g_cnt[t * 4] = make_int4(0, 0, 0, 0);
}

// One edge per thread: 2 counter bumps + 2 bucket stores.
__global__ void k_permute(const int* __restrict__ eu, const int* __restrict__ ei,
                          const float* __restrict__ nrm) {
    int e = blockIdx.x * blockDim.x + threadIdx.x;
    if (e >= N_EDGES) return;
    int u = __ldg(eu + e);
    int i = __ldg(ei + e);
    int wbits = __float_as_int(__ldg(nrm + e));
    int ni = N_USERS + i;
    int s1 = atomicAdd(&g_cnt[ni], 1);            // item dst <- user src
    g_csr[(ni << CAPLOG) + s1] = make_int2(u, wbits);
    int s2 = atomicAdd(&g_cnt[u], 1);             // user dst <- item src
    g_csr[(u << CAPLOG) + s2] = make_int2(i, wbits);
}

// ---------------- propagation layer: 8 lanes/node x 2 columns --------------
// Lanes 0-7 of each node-group jointly load 8 CSR entries (coalesced 64B),
// distribute premultiplied row offsets via width-8 shuffles; each lane loads
// columns (lane) and (lane+8) per edge -> 4 independent loads per unrolled pair.

__global__ void __launch_bounds__(256)
k_layer(const float4* __restrict__ uf, const float4* __restrict__ itf, int layer) {
    int t = blockIdx.x * blockDim.x + threadIdx.x;
    int n = t >> 3;
    int lane = t & 7;
    unsigned qmask = 0xFFu << (8 * ((threadIdx.x >> 3) & 3));

    const float4* src;
    float4* dst;
    if (n < N_USERS) {
        src = (layer == 0) ? itf : g_i[layer - 1];
        dst = &g_u[layer][(n << 4) + lane];
    } else {
        src = (layer == 0) ? uf : g_u[layer - 1];
        dst = &g_i[layer][((n - N_USERS) << 4) + lane];
    }

    int beg = n << CAPLOG;
    int end = beg + __ldg(&g_cnt[n]);

    float4 a0 = make_float4(0.f, 0.f, 0.f, 0.f);
    float4 b0 = a0, a1 = a0, b1 = a0;

    for (int base = beg; base < end; base += 8) {
        int k = base + lane;
        int2 p = (k < end) ? __ldg(&g_csr[k]) : make_int2(0, 0);
        int poff = p.x << 4;
        int cnt = end - base;
        if (cnt > 8) cnt = 8;

        int m = 0;
        for (; m + 1 < cnt; m += 2) {
            int s0  = __shfl_sync(qmask, poff, m,     8);
            int w0b = __shfl_sync(qmask, p.y,  m,     8);
            int s1  = __shfl_sync(qmask, poff, m + 1, 8);
            int w1b = __shfl_sync(qmask, p.y,  m + 1, 8);
            float4 r0a = __ldg(src + s0 + lane);
            float4 r0b = __ldg(src + s0 + lane + 8);
            float4 r1a = __ldg(src + s1 + lane);
            float4 r1b = __ldg(src + s1 + lane + 8);
            float w0 = __int_as_float(w0b);
            float w1 = __int_as_float(w1b);
            a0.x += r0a.x * w0; a0.y += r0a.y * w0; a0.z += r0a.z * w0; a0.w += r0a.w * w0;
            b0.x += r0b.x * w0; b0.y += r0b.y * w0; b0.z += r0b.z * w0; b0.w += r0b.w * w0;
            a1.x += r1a.x * w1; a1.y += r1a.y * w1; a1.z += r1a.z * w1; a1.w += r1a.w * w1;
            b1.x += r1b.x * w1; b1.y += r1b.y * w1; b1.z += r1b.z * w1; b1.w += r1b.w * w1;
        }
        if (m < cnt) {
            int s0  = __shfl_sync(qmask, poff, m, 8);
            int w0b = __shfl_sync(qmask, p.y,  m, 8);
            float4 r0a = __ldg(src + s0 + lane);
            float4 r0b = __ldg(src + s0 + lane + 8);
            float w0 = __int_as_float(w0b);
            a0.x += r0a.x * w0; a0.y += r0a.y * w0; a0.z += r0a.z * w0; a0.w += r0a.w * w0;
            b0.x += r0b.x * w0; b0.y += r0b.y * w0; b0.z += r0b.z * w0; b0.w += r0b.w * w0;
        }
    }

    dst[0] = make_float4(a0.x + a1.x, a0.y + a1.y, a0.z + a1.z, a0.w + a1.w);
    dst[8] = make_float4(b0.x + b1.x, b0.y + b1.y, b0.z + b1.z, b0.w + b1.w);
}

// ---------------- final batched lookup ----------------

__global__ void k_gather(const float4* __restrict__ uf, const float4* __restrict__ itf,
                         const int* __restrict__ users, const int* __restrict__ pos,
                         const int* __restrict__ neg, float4* __restrict__ out) {
    int t = blockIdx.x * blockDim.x + threadIdx.x;
    const int total = 3 * BATCH * DV;
    if (t >= total) return;
    int sec  = t / (BATCH * DV);
    int rem  = t % (BATCH * DV);
    int r    = rem / DV;
    int lane = rem % DV;

    float4 acc;
    if (sec == 0) {
        int idx = (__ldg(users + r) << 4) + lane;
        float4 a = uf[idx], b = g_u[0][idx], c = g_u[1][idx], d = g_u[2][idx];
        acc = make_float4(a.x + b.x + c.x + d.x, a.y + b.y + c.y + d.y,
                          a.z + b.z + c.z + d.z, a.w + b.w + c.w + d.w);
    } else {
        int idx = (((sec == 1) ? __ldg(pos + r) : __ldg(neg + r)) << 4) + lane;
        float4 a = itf[idx], b = g_i[0][idx], c = g_i[1][idx], d = g_i[2][idx];
        acc = make_float4(a.x + b.x + c.x + d.x, a.y + b.y + c.y + d.y,
                          a.z + b.z + c.z + d.z, a.w + b.w + c.w + d.w);
    }
    const float s = 0.25f;
    out[t] = make_float4(acc.x * s, acc.y * s, acc.z * s, acc.w * s);
}

extern "C" void kernel_launch(void* const* d_in, const int* in_sizes, int n_in,
                              void* d_out, int out_size) {
    const float4* user_feat = (const float4*)d_in[0];
    const float4* item_feat = (const float4*)d_in[1];
    const int*    edge_u    = (const int*)d_in[2];
    const int*    edge_i    = (const int*)d_in[3];
    const float*  nrm       = (const float*)d_in[4];
    const int*    users     = (const int*)d_in[5];
    const int*    pos       = (const int*)d_in[6];
    const int*    neg       = (const int*)d_in[7];
    float4*       out       = (float4*)d_out;

    const int TPB = 256;

    k_zero_cnt<<<(NT / 4 + TPB - 1) / TPB, TPB>>>();
    k_permute<<<(N_EDGES + TPB - 1) / TPB, TPB>>>(edge_u, edge_i, nrm);

    const int lt = NT * 8;                        // 2.4M threads, exact
    const int layer_blocks = lt / TPB;
    for (int l = 0; l < 3; l++)
        k_layer<<<layer_blocks, TPB>>>(user_feat, item_feat, l);

    const int gt_total = 3 * BATCH * DV;
    k_gather<<<(gt_total + TPB - 1) / TPB, TPB>>>(user_feat, item_feat, users, pos, neg, out);
}